// round 5
// baseline (speedup 1.0000x reference)
#include <cuda_runtime.h>
#include <math.h>

#define BB 32
#define NN 2048
#define MM 2048
#define TPB 64
#define BPB (NN / TPB)         // 32 blocks per batch
#define NBLK (BB * BPB)        // 1024 blocks; 7/SM -> single wave
#define PAIRS (MM / 2)
#define LOG2E 1.4426950408889634f
#define CSHIFT 64.0f           // global log2-domain shift (cancels in softmax ratio)

// Scratch (no allocations allowed)
__device__ float g_T[2][BB * 4];        // parity-buffered transforms: c, s, tx, ty
__device__ float g_part[NBLK * 8];      // per-block partial sums

typedef unsigned long long ull;

__device__ __forceinline__ ull pk(float a, float b) {
    ull r; asm("mov.b64 %0,{%1,%2};" : "=l"(r) : "f"(a), "f"(b)); return r;
}
__device__ __forceinline__ void upk(ull v, float& a, float& b) {
    asm("mov.b64 {%0,%1},%2;" : "=f"(a), "=f"(b) : "l"(v));
}
__device__ __forceinline__ ull fma2(ull a, ull b, ull c) {
    ull r; asm("fma.rn.f32x2 %0,%1,%2,%3;" : "=l"(r) : "l"(a), "l"(b), "l"(c)); return r;
}
__device__ __forceinline__ ull add2(ull a, ull b) {
    ull r; asm("add.rn.f32x2 %0,%1,%2;" : "=l"(r) : "l"(a), "l"(b)); return r;
}
__device__ __forceinline__ float ex2(float x) {
    float y; asm("ex2.approx.ftz.f32 %0,%1;" : "=f"(y) : "f"(x)); return y;
}

// ---------------------------------------------------------------------------
// Kabsch delta from 8 reduced sums v[], composed with previous transform.
// Polar factor of H^T == V U^T of the SVD incl. the det<0 reflection case.
// Pure fp32, identical instruction sequence everywhere -> deterministic.
// ---------------------------------------------------------------------------
__device__ __forceinline__ void kabsch_compose(const float* v,
                                               float oc, float os, float ox, float oy,
                                               float& nc, float& ns,
                                               float& ntx, float& nty) {
    const float inN = 1.0f / (float)NN;
    const float csx = v[0] * inN, csy = v[1] * inN;
    const float ctx = v[2] * inN, cty = v[3] * inN;
    const float H00 = v[4] - v[0] * v[2] * inN;
    const float H01 = v[5] - v[0] * v[3] * inN;
    const float H10 = v[6] - v[1] * v[2] * inN;
    const float H11 = v[7] - v[1] * v[3] * inN;

    const float b0 = H00 + H11, b1 = H10 - H01;   // rotation part
    const float c0 = H00 - H11, c1 = H10 + H01;   // reflection part
    const float nb  = b0 * b0 + b1 * b1;
    const float nc2 = c0 * c0 + c1 * c1;

    float R00, R01, R10, R11;
    if (nb >= nc2) {
        float ih = (nb > 0.f) ? rsqrtf(nb) : 0.f;
        R00 = b0 * ih;  R01 = b1 * ih;
        R10 = -b1 * ih; R11 = b0 * ih;
    } else {
        float ih = (nc2 > 0.f) ? rsqrtf(nc2) : 0.f;
        R00 = c0 * ih;  R01 = c1 * ih;
        R10 = c1 * ih;  R11 = -c0 * ih;
    }
    const float tdx = ctx - (R00 * csx + R01 * csy);
    const float tdy = cty - (R10 * csx + R11 * csy);

    // Applied delta rotation = normalize(R00, R10) (matches vec2mat(atan2)).
    const float nn2 = R00 * R00 + R10 * R10;
    const float inh = (nn2 > 0.f) ? rsqrtf(nn2) : 0.f;
    const float cd = R00 * inh, sd = R10 * inh;

    nc  = cd * oc - sd * os;
    ns  = sd * oc + cd * os;
    ntx = cd * ox - sd * oy + tdx;
    nty = sd * ox + cd * oy + tdy;
}

// ---------------------------------------------------------------------------
// Fused iteration + folded-in update prologue.
// grid = 1024, block = 64. One source row per thread.
// smem: 24KB packed-pair target tile (f32x2 operand layout).
// ---------------------------------------------------------------------------
__global__ __launch_bounds__(TPB, 7)
void iter_kernel(const float* __restrict__ source,
                 const float* __restrict__ target,
                 const float* __restrict__ init,
                 int it) {
    __shared__ ull  smX[PAIRS];    // 8 KB: (tx0, tx1) packed pairs
    __shared__ ull  smY[PAIRS];    // 8 KB: (ty0, ty1)
    __shared__ ull  smK[PAIRS];    // 8 KB: (c0, c1), c = -log2e*|t|^2 - CSHIFT
    __shared__ float red[2][8];
    __shared__ float sT[4];

    const int tid = threadIdx.x;
    const int b   = blockIdx.x >> 5;
    const int blk = blockIdx.x & 31;

    // Issue partial-sum loads early (prologue of the folded update, it >= 1).
    float4 qa = make_float4(0.f, 0.f, 0.f, 0.f), qb = qa;
    if (it > 0 && tid < 32) {
        const float4* pp = (const float4*)&g_part[(b * BPB + tid) * 8];
        qa = pp[0]; qb = pp[1];
    }

    // ---- smem fill: raw target -> packed-pair coefficients ----
    const float4* tg = (const float4*)(target + (size_t)b * MM * 2);
#pragma unroll
    for (int i = 0; i < PAIRS / TPB; i++) {    // 16 iterations
        int p = tid + i * TPB;
        float4 q = tg[p];                      // tx0, ty0, tx1, ty1
        smX[p] = pk(q.x, q.z);
        smY[p] = pk(q.y, q.w);
        smK[p] = pk(fmaf(-LOG2E, q.x * q.x + q.y * q.y, -CSHIFT),
                    fmaf(-LOG2E, q.z * q.z + q.w * q.w, -CSHIFT));
    }

    // ---- folded update: warp 0 reduces partials, lane 0 composes T ----
    if (it > 0 && tid < 32) {
        float v[8] = {qa.x, qa.y, qa.z, qa.w, qb.x, qb.y, qb.z, qb.w};
#pragma unroll
        for (int off = 16; off > 0; off >>= 1)
#pragma unroll
            for (int k = 0; k < 8; k++)
                v[k] += __shfl_down_sync(0xffffffffu, v[k], off);
        if (tid == 0) {
            float oc, os, ox, oy;
            if (it == 1) {
                float th = init[b * 3 + 0];
                oc = cosf(th); os = sinf(th);
                ox = init[b * 3 + 1]; oy = init[b * 3 + 2];
            } else {
                const float* pT = &g_T[(it - 1) & 1][b * 4];
                oc = pT[0]; os = pT[1]; ox = pT[2]; oy = pT[3];
            }
            float nc, ns, ntx, nty;
            kabsch_compose(v, oc, os, ox, oy, nc, ns, ntx, nty);
            sT[0] = nc; sT[1] = ns; sT[2] = ntx; sT[3] = nty;
            float* wT = &g_T[it & 1][b * 4];   // duplicate identical writes OK
            wT[0] = nc; wT[1] = ns; wT[2] = ntx; wT[3] = nty;
        }
    } else if (it == 0 && tid == 0) {
        float th = init[b * 3 + 0];
        sT[0] = cosf(th); sT[1] = sinf(th);
        sT[2] = init[b * 3 + 1]; sT[3] = init[b * 3 + 2];
    }
    __syncthreads();

    const float Tc = sT[0], Ts = sT[1], Tx = sT[2], Ty = sT[3];
    const int row = blk * TPB + tid;
    const float2 s2 = ((const float2*)source)[b * NN + row];
    const float stx = Tc * s2.x - Ts * s2.y + Tx;
    const float sty = Ts * s2.x + Tc * s2.y + Ty;
    const ull px2 = pk(2.f * LOG2E * stx, 2.f * LOG2E * stx);
    const ull py2 = pk(2.f * LOG2E * sty, 2.f * LOG2E * sty);

    // ---- mainloop: per pair = 2 FFMA2 + 2 MUFU + 3 packed acc ----
    ull sa = 0ull, axa = 0ull, aya = 0ull;
#pragma unroll 8
    for (int p = 0; p < PAIRS; p++) {
        ull tx = smX[p];
        ull ty = smY[p];
        ull cc = smK[p];
        ull l  = fma2(px2, tx, fma2(py2, ty, cc));
        float l0, l1; upk(l, l0, l1);
        ull e  = pk(ex2(l0), ex2(l1));
        sa  = add2(sa, e);
        axa = fma2(e, tx, axa);
        aya = fma2(e, ty, aya);
    }

    float sl, sh, axl, axh, ayl, ayh;
    upk(sa, sl, sh); upk(axa, axl, axh); upk(aya, ayl, ayh);
    const float inv = 1.0f / (sl + sh);
    const float tcx = (axl + axh) * inv;
    const float tcy = (ayl + ayh) * inv;

    // ---- 8-term block reduction ----
    float v[8];
    v[0] = stx;       v[1] = sty;
    v[2] = tcx;       v[3] = tcy;
    v[4] = stx * tcx; v[5] = stx * tcy;
    v[6] = sty * tcx; v[7] = sty * tcy;
#pragma unroll
    for (int off = 16; off > 0; off >>= 1)
#pragma unroll
        for (int k = 0; k < 8; k++)
            v[k] += __shfl_down_sync(0xffffffffu, v[k], off);
    const int wid = tid >> 5, lane = tid & 31;
    if (lane == 0)
#pragma unroll
        for (int k = 0; k < 8; k++) red[wid][k] = v[k];
    __syncthreads();
    if (tid < 8)
        g_part[(b * BPB + blk) * 8 + tid] = red[0][tid] + red[1][tid];
}

// ---------------------------------------------------------------------------
// Final update after iteration 4: compose last delta, emit output.
// 1 block x 1024 threads, warp w = batch w.
// ---------------------------------------------------------------------------
__global__ __launch_bounds__(BB * 32)
void final_kernel(float* __restrict__ out) {
    const int b    = threadIdx.x >> 5;
    const int lane = threadIdx.x & 31;

    const float4* p = (const float4*)&g_part[(b * BPB + lane) * 8];
    float4 qa = p[0];
    float4 qb = p[1];
    float v[8] = {qa.x, qa.y, qa.z, qa.w, qb.x, qb.y, qb.z, qb.w};
#pragma unroll
    for (int off = 16; off > 0; off >>= 1)
#pragma unroll
        for (int k = 0; k < 8; k++)
            v[k] += __shfl_down_sync(0xffffffffu, v[k], off);
    if (lane != 0) return;

    // prev T = T_4, written during iter it=4's prologue into parity buffer 0.
    const float* pT = &g_T[0][b * 4];
    float nc, ns, ntx, nty;
    kabsch_compose(v, pT[0], pT[1], pT[2], pT[3], nc, ns, ntx, nty);

    out[b * 3 + 0] = atan2f(ns, nc);
    out[b * 3 + 1] = ntx;
    out[b * 3 + 2] = nty;
}

// ---------------------------------------------------------------------------
extern "C" void kernel_launch(void* const* d_in, const int* in_sizes, int n_in,
                              void* d_out, int out_size) {
    const float* source = (const float*)d_in[0];
    const float* target = (const float*)d_in[1];
    const float* init   = (const float*)d_in[2];
    float* out = (float*)d_out;

    for (int it = 0; it < 5; it++)
        iter_kernel<<<NBLK, TPB>>>(source, target, init, it);
    final_kernel<<<1, BB * 32>>>(out);
}

// round 6
// speedup vs baseline: 1.4064x; 1.4064x over previous
#include <cuda_runtime.h>
#include <math.h>

#define BB 32
#define NN 2048
#define MM 2048
#define TPB 64
#define BPB (NN / TPB)         // 32 blocks per batch
#define NBLK (BB * BPB)        // 1024 blocks; ~7/SM -> single wave
#define LOG2E 1.4426950408889634f
#define CSHIFT 64.0f           // global log2-domain shift (cancels in softmax ratio)

// Scratch (no allocations allowed)
__device__ float g_T[2][BB * 4];        // parity-buffered transforms: c, s, tx, ty
__device__ float g_part[NBLK * 8];      // per-block partial sums

__device__ __forceinline__ float ex2(float x) {
    float y;
    asm("ex2.approx.ftz.f32 %0, %1;" : "=f"(y) : "f"(x));
    return y;
}

// ---------------------------------------------------------------------------
// Kabsch delta from 8 reduced sums v[], composed with previous transform.
// Polar factor of H^T == V U^T of the SVD incl. the det<0 reflection case.
// Pure fp32, identical instruction sequence everywhere -> deterministic.
// ---------------------------------------------------------------------------
__device__ __forceinline__ void kabsch_compose(const float* v,
                                               float oc, float os, float ox, float oy,
                                               float& nc, float& ns,
                                               float& ntx, float& nty) {
    const float inN = 1.0f / (float)NN;
    const float csx = v[0] * inN, csy = v[1] * inN;
    const float ctx = v[2] * inN, cty = v[3] * inN;
    const float H00 = v[4] - v[0] * v[2] * inN;
    const float H01 = v[5] - v[0] * v[3] * inN;
    const float H10 = v[6] - v[1] * v[2] * inN;
    const float H11 = v[7] - v[1] * v[3] * inN;

    const float b0 = H00 + H11, b1 = H10 - H01;   // rotation part
    const float c0 = H00 - H11, c1 = H10 + H01;   // reflection part
    const float nb  = b0 * b0 + b1 * b1;
    const float nc2 = c0 * c0 + c1 * c1;

    float R00, R01, R10, R11;
    if (nb >= nc2) {
        float ih = (nb > 0.f) ? rsqrtf(nb) : 0.f;
        R00 = b0 * ih;  R01 = b1 * ih;
        R10 = -b1 * ih; R11 = b0 * ih;
    } else {
        float ih = (nc2 > 0.f) ? rsqrtf(nc2) : 0.f;
        R00 = c0 * ih;  R01 = c1 * ih;
        R10 = c1 * ih;  R11 = -c0 * ih;
    }
    const float tdx = ctx - (R00 * csx + R01 * csy);
    const float tdy = cty - (R10 * csx + R11 * csy);

    // Applied delta rotation = normalize(R00, R10) (matches vec2mat(atan2)).
    const float nn2 = R00 * R00 + R10 * R10;
    const float inh = (nn2 > 0.f) ? rsqrtf(nn2) : 0.f;
    const float cd = R00 * inh, sd = R10 * inh;

    nc  = cd * oc - sd * os;
    ns  = sd * oc + cd * os;
    ntx = cd * ox - sd * oy + tdx;
    nty = sd * ox + cd * oy + tdy;
}

// ---------------------------------------------------------------------------
// Fused iteration + folded-in update prologue.
// grid = 1024, block = 64. One source row per thread.
// Mainloop = R4 scalar version (measured at the 5-FFMA/element pipe ceiling).
// ---------------------------------------------------------------------------
__global__ __launch_bounds__(TPB, 7)
void iter_kernel(const float* __restrict__ source,
                 const float* __restrict__ target,
                 const float* __restrict__ init,
                 int it) {
    __shared__ float2 smT[MM];     // 16 KB: (tx, ty)
    __shared__ float  smC[MM];     //  8 KB: -log2e*|t|^2 - CSHIFT
    __shared__ float  red[2][8];
    __shared__ float  sT[4];

    const int tid = threadIdx.x;
    const int b   = blockIdx.x >> 5;
    const int blk = blockIdx.x & 31;

    // Issue partial-sum loads early (prologue of the folded update, it >= 1).
    float4 qa = make_float4(0.f, 0.f, 0.f, 0.f), qb = qa;
    if (it > 0 && tid < 32) {
        const float4* pp = (const float4*)&g_part[(b * BPB + tid) * 8];
        qa = pp[0]; qb = pp[1];
    }

    // ---- smem fill: raw target -> coefficients ----
    const float4* tg = (const float4*)(target + (size_t)b * MM * 2);
#pragma unroll
    for (int i = 0; i < MM / 2 / TPB; i++) {   // 16 iterations, 2 points each
        int p = tid + i * TPB;
        float4 q = tg[p];                      // tx0, ty0, tx1, ty1
        smT[2 * p + 0] = make_float2(q.x, q.y);
        smT[2 * p + 1] = make_float2(q.z, q.w);
        smC[2 * p + 0] = fmaf(-LOG2E, q.x * q.x + q.y * q.y, -CSHIFT);
        smC[2 * p + 1] = fmaf(-LOG2E, q.z * q.z + q.w * q.w, -CSHIFT);
    }

    // ---- folded update: warp 0 reduces partials, lane 0 composes T ----
    if (it > 0 && tid < 32) {
        float v[8] = {qa.x, qa.y, qa.z, qa.w, qb.x, qb.y, qb.z, qb.w};
#pragma unroll
        for (int off = 16; off > 0; off >>= 1)
#pragma unroll
            for (int k = 0; k < 8; k++)
                v[k] += __shfl_down_sync(0xffffffffu, v[k], off);
        if (tid == 0) {
            float oc, os, ox, oy;
            if (it == 1) {
                float th = init[b * 3 + 0];
                oc = cosf(th); os = sinf(th);
                ox = init[b * 3 + 1]; oy = init[b * 3 + 2];
            } else {
                const float* pT = &g_T[(it - 1) & 1][b * 4];
                oc = pT[0]; os = pT[1]; ox = pT[2]; oy = pT[3];
            }
            float nc, ns, ntx, nty;
            kabsch_compose(v, oc, os, ox, oy, nc, ns, ntx, nty);
            sT[0] = nc; sT[1] = ns; sT[2] = ntx; sT[3] = nty;
            float* wT = &g_T[it & 1][b * 4];   // identical duplicate writes OK
            wT[0] = nc; wT[1] = ns; wT[2] = ntx; wT[3] = nty;
        }
    } else if (it == 0 && tid == 0) {
        float th = init[b * 3 + 0];
        sT[0] = cosf(th); sT[1] = sinf(th);
        sT[2] = init[b * 3 + 1]; sT[3] = init[b * 3 + 2];
    }
    __syncthreads();

    const float Tc = sT[0], Ts = sT[1], Tx = sT[2], Ty = sT[3];
    const int row = blk * TPB + tid;
    const float2 s2 = ((const float2*)source)[b * NN + row];
    const float stx = Tc * s2.x - Ts * s2.y + Tx;
    const float sty = Ts * s2.x + Tc * s2.y + Ty;
    const float px  = 2.f * LOG2E * stx;
    const float py  = 2.f * LOG2E * sty;

    // ---- mainloop: 5 fma-pipe ops + 1 MUFU per element (at pipe ceiling) ----
    float s0 = 0.f, s1 = 0.f;
    float ax0 = 0.f, ax1 = 0.f;
    float ay0 = 0.f, ay1 = 0.f;

#pragma unroll 8
    for (int m = 0; m < MM; m += 2) {
        float2 t0 = smT[m + 0];
        float2 t1 = smT[m + 1];
        float  c0 = smC[m + 0];
        float  c1 = smC[m + 1];
        float e0 = ex2(fmaf(px, t0.x, fmaf(py, t0.y, c0)));
        float e1 = ex2(fmaf(px, t1.x, fmaf(py, t1.y, c1)));
        s0 += e0; ax0 = fmaf(e0, t0.x, ax0); ay0 = fmaf(e0, t0.y, ay0);
        s1 += e1; ax1 = fmaf(e1, t1.x, ax1); ay1 = fmaf(e1, t1.y, ay1);
    }

    const float inv = 1.0f / (s0 + s1);
    const float tcx = (ax0 + ax1) * inv;
    const float tcy = (ay0 + ay1) * inv;

    // ---- 8-term block reduction ----
    float v[8];
    v[0] = stx;       v[1] = sty;
    v[2] = tcx;       v[3] = tcy;
    v[4] = stx * tcx; v[5] = stx * tcy;
    v[6] = sty * tcx; v[7] = sty * tcy;
#pragma unroll
    for (int off = 16; off > 0; off >>= 1)
#pragma unroll
        for (int k = 0; k < 8; k++)
            v[k] += __shfl_down_sync(0xffffffffu, v[k], off);
    const int wid = tid >> 5, lane = tid & 31;
    if (lane == 0)
#pragma unroll
        for (int k = 0; k < 8; k++) red[wid][k] = v[k];
    __syncthreads();
    if (tid < 8)
        g_part[(b * BPB + blk) * 8 + tid] = red[0][tid] + red[1][tid];
}

// ---------------------------------------------------------------------------
// Final update after iteration 4: compose last delta, emit output.
// 1 block x 1024 threads, warp w = batch w.
// ---------------------------------------------------------------------------
__global__ __launch_bounds__(BB * 32)
void final_kernel(float* __restrict__ out) {
    const int b    = threadIdx.x >> 5;
    const int lane = threadIdx.x & 31;

    const float4* p = (const float4*)&g_part[(b * BPB + lane) * 8];
    float4 qa = p[0];
    float4 qb = p[1];
    float v[8] = {qa.x, qa.y, qa.z, qa.w, qb.x, qb.y, qb.z, qb.w};
#pragma unroll
    for (int off = 16; off > 0; off >>= 1)
#pragma unroll
        for (int k = 0; k < 8; k++)
            v[k] += __shfl_down_sync(0xffffffffu, v[k], off);
    if (lane != 0) return;

    // prev T = T_4, written during iter it=4's prologue into parity buffer 0.
    const float* pT = &g_T[0][b * 4];
    float nc, ns, ntx, nty;
    kabsch_compose(v, pT[0], pT[1], pT[2], pT[3], nc, ns, ntx, nty);

    out[b * 3 + 0] = atan2f(ns, nc);
    out[b * 3 + 1] = ntx;
    out[b * 3 + 2] = nty;
}

// ---------------------------------------------------------------------------
extern "C" void kernel_launch(void* const* d_in, const int* in_sizes, int n_in,
                              void* d_out, int out_size) {
    const float* source = (const float*)d_in[0];
    const float* target = (const float*)d_in[1];
    const float* init   = (const float*)d_in[2];
    float* out = (float*)d_out;

    for (int it = 0; it < 5; it++)
        iter_kernel<<<NBLK, TPB>>>(source, target, init, it);
    final_kernel<<<1, BB * 32>>>(out);
}